// round 10
// baseline (speedup 1.0000x reference)
#include <cuda_runtime.h>
#include <math.h>
#include <cstdint>

// Problem constants
#define BB    8
#define CC    128
#define HIN   62
#define HH    64
#define WW    64
#define GG    4
#define GCC   32
#define PP    9
#define NPOS  (BB*HH*WW)   // 32768

// Scratch (device globals; no allocation allowed)
__device__ float g_xt[NPOS*CC];
__device__ float g_y[NPOS*CC];
__device__ float g_xproj[NPOS*CC];
__device__ float g_dg[NPOS*CC];
__device__ float g_samp[NPOS*CC];
__device__ float g_om[NPOS*CC];
__device__ float g_w1T[CC*CC];
__device__ float g_w2P[CC*CC];
__device__ float g_w3T[CC*CC];
__device__ float g_b2[CC];

// ===========================================================================
__device__ __forceinline__ uint32_t f2tf32(float f) {
    uint32_t r;
    asm("cvt.rna.tf32.f32 %0, %1;" : "=r"(r) : "f"(f));
    return r;
}
__device__ __forceinline__ void mma_tf32(float* c, const uint32_t* a, const uint32_t* b) {
    asm volatile(
        "mma.sync.aligned.m16n8k8.row.col.f32.tf32.tf32.f32 "
        "{%0,%1,%2,%3}, {%4,%5,%6,%7}, {%8,%9}, {%0,%1,%2,%3};"
        : "+f"(c[0]), "+f"(c[1]), "+f"(c[2]), "+f"(c[3])
        : "r"(a[0]), "r"(a[1]), "r"(a[2]), "r"(a[3]), "r"(b[0]), "r"(b[1]));
}
__device__ __forceinline__ uint32_t smem_u32(const void* p) {
    uint32_t a;
    asm("{ .reg .u64 t; cvta.to.shared.u64 t, %1; cvt.u32.u64 %0, t; }" : "=r"(a) : "l"(p));
    return a;
}
#define CP_ASYNC16(dst, src) \
    asm volatile("cp.async.cg.shared.global [%0], [%1], 16;" \
        :: "r"(dst), "l"(__cvta_generic_to_global(src)) : "memory")
#define CP_COMMIT() asm volatile("cp.async.commit_group;" ::: "memory")
#define CP_WAIT(n)  asm volatile("cp.async.wait_group %0;" :: "n"(n) : "memory")

// ===========================================================================
// Weight prep
// ===========================================================================
__global__ void prep_weights_kernel(const float* __restrict__ w1, const float* __restrict__ w3,
                                    const float* __restrict__ offw, const float* __restrict__ maskw,
                                    const float* __restrict__ offb, const float* __restrict__ maskb,
                                    float* __restrict__ w1T, float* __restrict__ w3T,
                                    float* __restrict__ w2P, float* __restrict__ b2) {
    const int n = blockIdx.x, k = threadIdx.x;
    w1T[n * CC + k] = w1[k * CC + n];
    w3T[n * CC + k] = w3[k * CC + n];
    float v = 0.f;
    if (n < 72)       v = offw[k * 72 + n];
    else if (n < 108) v = maskw[k * 36 + (n - 72)];
    w2P[n * CC + k] = v;
    if (k == 0) b2[n] = (n < 72) ? offb[n] : ((n < 108) ? maskb[n - 72] : 0.f);
}

// ===========================================================================
// x NCHW -> NHWC with 1-px zero border
// ===========================================================================
__global__ void pack_x_kernel(const float* __restrict__ x, float* __restrict__ xt) {
    __shared__ float t[32][33];
    const int b  = blockIdx.z >> 6;
    const int h  = blockIdx.z & 63;
    const int w0 = blockIdx.x * 32;
    const int c0 = blockIdx.y * 32;
    const int tx = threadIdx.x, ty = threadIdx.y;
    const int hh = h - 1;
    const int ww = w0 + tx - 1;
    const int cc = c0 + ty;
    float v = 0.f;
    if (hh >= 0 && hh < HIN && ww >= 0 && ww < HIN)
        v = x[(((size_t)b * CC + cc) * HIN + hh) * HIN + ww];
    t[ty][tx] = v;
    __syncthreads();
    xt[(((size_t)b * HH + h) * WW + (w0 + ty)) * CC + (c0 + tx)] = t[tx][ty];
}

// ===========================================================================
// HMMA tf32 GEMM: tile M64 x N64, K chunked 2x64 via cp.async double buffer.
// CTA = 256 threads = 8 warps (4m x 2n); warp tile = 16 rows x 32 cols.
// smem: 2 stages x (64 A rows + 64 B rows) x 68 = 69632 B -> 3 CTAs/SM.
// TO_NCHW=true: epilogue transposes via smem, writes NCHW directly.
// ===========================================================================
#define CH      64
#define CPITCH  68
#define STAGE_F (128 * CPITCH)            // floats per stage (64 A + 64 B rows)
#define GEMM_SMEM (2 * STAGE_F * 4)       // 69632 bytes
#define EPITCH  68                         // epilogue staging pitch

template <bool TO_NCHW>
__global__ void __launch_bounds__(256, 3)
hmma_gemm_kernel(const float* __restrict__ A, const float* __restrict__ Bm,
                 const float* __restrict__ bias, float* __restrict__ Cout) {
    extern __shared__ float smem[];
    const uint32_t sbase = smem_u32(smem);

    const int tid  = threadIdx.x;
    const int lane = tid & 31;
    const int wid  = tid >> 5;
    const int gid  = lane >> 2;
    const int tg   = lane & 3;
    const int warp_m = wid & 3;   // 4 subtiles of 16 rows
    const int warp_n = wid >> 2;  // 2 subtiles of 32 cols
    const int m0 = blockIdx.x * 64;
    const int n0 = blockIdx.y * 64;

    // ---- issue one K-chunk into stage s (8 cp.async.16 per thread) ----
    const int irow = tid >> 4;            // 0..15
    const int ic   = (tid & 15) * 4;      // float offset within chunk row
    auto issue = [&](int s, int kc) {
        const uint32_t st = sbase + (uint32_t)(s * STAGE_F * 4);
        #pragma unroll
        for (int i = 0; i < 4; i++) {
            const int row = irow + i * 16;
            CP_ASYNC16(st + (uint32_t)((row * CPITCH + ic) * 4),
                       A + (size_t)(m0 + row) * CC + kc + ic);
        }
        #pragma unroll
        for (int i = 0; i < 4; i++) {
            const int row = irow + i * 16;
            CP_ASYNC16(st + (uint32_t)(((64 + row) * CPITCH + ic) * 4),
                       Bm + (size_t)(n0 + row) * CC + kc + ic);
        }
        CP_COMMIT();
    };

    issue(0, 0);
    issue(1, CH);

    float acc[4][4];
    #pragma unroll
    for (int ni = 0; ni < 4; ni++)
        #pragma unroll
        for (int j = 0; j < 4; j++) acc[ni][j] = 0.f;

    const int arow0 = warp_m * 16 + gid;
    const int bcol0 = warp_n * 32 + gid;

    auto mma_chunk = [&](int s) {
        const float* uA = smem + s * STAGE_F;
        const float* uB = uA + 64 * CPITCH;
        #pragma unroll
        for (int ks = 0; ks < 8; ks++) {
            const int k8 = ks * 8;
            uint32_t af[4];
            af[0] = f2tf32(uA[(arow0    ) * CPITCH + k8 + tg]);
            af[1] = f2tf32(uA[(arow0 + 8) * CPITCH + k8 + tg]);
            af[2] = f2tf32(uA[(arow0    ) * CPITCH + k8 + tg + 4]);
            af[3] = f2tf32(uA[(arow0 + 8) * CPITCH + k8 + tg + 4]);
            #pragma unroll
            for (int ni = 0; ni < 4; ni++) {
                const int n = bcol0 + ni * 8;
                uint32_t bf[2];
                bf[0] = f2tf32(uB[n * CPITCH + k8 + tg]);
                bf[1] = f2tf32(uB[n * CPITCH + k8 + tg + 4]);
                mma_tf32(acc[ni], af, bf);
            }
        }
    };

    CP_WAIT(1);
    __syncthreads();
    mma_chunk(0);
    CP_WAIT(0);
    __syncthreads();
    mma_chunk(1);

    float2 bb[4];
    #pragma unroll
    for (int ni = 0; ni < 4; ni++) {
        const int col = n0 + warp_n * 32 + ni * 8 + 2 * tg;
        bb[ni].x = __ldg(bias + col);
        bb[ni].y = __ldg(bias + col + 1);
    }

    if (!TO_NCHW) {
        const int r0 = m0 + arow0;
        #pragma unroll
        for (int ni = 0; ni < 4; ni++) {
            const int col = n0 + warp_n * 32 + ni * 8 + 2 * tg;
            float2 v0 = make_float2(acc[ni][0] + bb[ni].x, acc[ni][1] + bb[ni].y);
            float2 v1 = make_float2(acc[ni][2] + bb[ni].x, acc[ni][3] + bb[ni].y);
            *reinterpret_cast<float2*>(Cout + (size_t)r0 * CC + col)       = v0;
            *reinterpret_cast<float2*>(Cout + (size_t)(r0 + 8) * CC + col) = v1;
        }
    } else {
        __syncthreads();   // done reading stage buffers
        float* sCT = smem;  // [64 cols][64 rows], pitch EPITCH
        #pragma unroll
        for (int ni = 0; ni < 4; ni++) {
            const int col = warp_n * 32 + ni * 8 + 2 * tg;
            const int r   = arow0;
            sCT[(col    ) * EPITCH + r    ] = acc[ni][0] + bb[ni].x;
            sCT[(col + 1) * EPITCH + r    ] = acc[ni][1] + bb[ni].y;
            sCT[(col    ) * EPITCH + r + 8] = acc[ni][2] + bb[ni].x;
            sCT[(col + 1) * EPITCH + r + 8] = acc[ni][3] + bb[ni].y;
        }
        __syncthreads();
        const int b       = m0 >> 12;
        const int inbatch = m0 & 4095;
        #pragma unroll
        for (int i = 0; i < 4; i++) {
            const int idx = i * 256 + tid;      // 1024 float4s: 64 cols x 16
            const int col = idx >> 4;
            const int rc  = idx & 15;
            const float4 v = *reinterpret_cast<const float4*>(sCT + col * EPITCH + rc * 4);
            *reinterpret_cast<float4*>(
                Cout + ((size_t)b * CC + (n0 + col)) * (HH * WW) + inbatch + rc * 4) = v;
        }
    }
}

// ===========================================================================
// Depthwise 3x3 (pad 1) + bias + LayerNorm(C) + exact GELU.
// ===========================================================================
__global__ void __launch_bounds__(256)
dw_ln_gelu_kernel(const float* __restrict__ y,
                  const float* __restrict__ dww,
                  const float* __restrict__ dwb,
                  const float* __restrict__ lng,
                  const float* __restrict__ lnb,
                  float* __restrict__ out) {
    __shared__ float sW[9 * CC];
    const int tid = threadIdx.x;
    for (int i = tid; i < 9 * CC; i += 256) {
        const int c = i / 9, tap = i % 9;
        sW[tap * CC + c] = dww[i];
    }
    __syncthreads();

    const int wid  = tid >> 5;
    const int lane = tid & 31;
    const int pos  = blockIdx.x * 8 + wid;
    const int b = pos >> 12;
    const int h = (pos >> 6) & 63;
    const int w = pos & 63;
    const int c4 = lane * 4;

    const float4 bv = __ldg(reinterpret_cast<const float4*>(dwb + c4));
    float4 acc = bv;
    const float* ybase = y + (((size_t)b * HH + h) * WW + w) * CC + c4;
    #pragma unroll
    for (int i = 0; i < 3; i++) {
        const int hh = h + i - 1;
        if ((unsigned)hh >= (unsigned)HH) continue;
        #pragma unroll
        for (int j = 0; j < 3; j++) {
            const int ww = w + j - 1;
            if ((unsigned)ww >= (unsigned)WW) continue;
            const float4 v = __ldg(reinterpret_cast<const float4*>(
                ybase + ((i - 1) * WW + (j - 1)) * CC));
            const float4 wt = *reinterpret_cast<const float4*>(sW + (i * 3 + j) * CC + c4);
            acc.x = fmaf(v.x, wt.x, acc.x);
            acc.y = fmaf(v.y, wt.y, acc.y);
            acc.z = fmaf(v.z, wt.z, acc.z);
            acc.w = fmaf(v.w, wt.w, acc.w);
        }
    }

    float s  = acc.x + acc.y + acc.z + acc.w;
    float s2 = acc.x * acc.x + acc.y * acc.y + acc.z * acc.z + acc.w * acc.w;
    #pragma unroll
    for (int o = 16; o > 0; o >>= 1) {
        s  += __shfl_xor_sync(0xFFFFFFFFu, s,  o);
        s2 += __shfl_xor_sync(0xFFFFFFFFu, s2, o);
    }
    const float mean = s * (1.f / CC);
    const float var  = s2 * (1.f / CC) - mean * mean;
    const float rstd = rsqrtf(var + 1e-5f);

    const float4 gv = __ldg(reinterpret_cast<const float4*>(lng + c4));
    const float4 betav = __ldg(reinterpret_cast<const float4*>(lnb + c4));
    float4 o4;
    {
        float v0 = (acc.x - mean) * rstd * gv.x + betav.x;
        float v1 = (acc.y - mean) * rstd * gv.y + betav.y;
        float v2 = (acc.z - mean) * rstd * gv.z + betav.z;
        float v3 = (acc.w - mean) * rstd * gv.w + betav.w;
        const float k = 0.70710678118654752440f;
        o4.x = 0.5f * v0 * (1.f + erff(v0 * k));
        o4.y = 0.5f * v1 * (1.f + erff(v1 * k));
        o4.z = 0.5f * v2 * (1.f + erff(v2 * k));
        o4.w = 0.5f * v3 * (1.f + erff(v3 * k));
    }
    *reinterpret_cast<float4*>(out + (size_t)pos * CC + c4) = o4;
}

// ===========================================================================
// DCNv3 bilinear sampler + fused group softmax.
// ===========================================================================
__global__ void __launch_bounds__(128)
sampler_kernel(const float* __restrict__ xproj,
               const float* __restrict__ om,
               float* __restrict__ out) {
    __shared__ float sOM[4][112];
    const int tid  = threadIdx.x;
    const int wid  = tid >> 5;
    const int lane = tid & 31;
    const int pos  = blockIdx.x * 4 + wid;
    const int b = pos >> 12;
    const int h = (pos >> 6) & 63;
    const int w = pos & 63;
    const int g  = lane >> 3;
    const int c4 = (lane & 7) * 4;

    #pragma unroll
    for (int r = 0; r < 4; r++) {
        const int i = r * 32 + lane;
        if (i < 108) sOM[wid][i] = __ldg(om + (size_t)pos * CC + i);
    }
    __syncwarp();

    const float* logit = &sOM[wid][72 + g * 9];
    float mx = -1e30f;
    #pragma unroll
    for (int p = 0; p < 9; p++) mx = fmaxf(mx, logit[p]);
    float se = 0.f;
    float ex[9];
    #pragma unroll
    for (int p = 0; p < 9; p++) { ex[p] = expf(logit[p] - mx); se += ex[p]; }
    const float inv_se = 1.f / se;

    const float* base = xproj + (size_t)b * (HH * WW * CC) + g * GCC + c4;
    float4 acc = make_float4(0.f, 0.f, 0.f, 0.f);
    #pragma unroll
    for (int p = 0; p < PP; p++) {
        const int gp = g * 9 + p;
        const float fix = (float)(w + p / 3) + sOM[wid][2 * gp];
        const float fiy = (float)(h + p % 3) + sOM[wid][2 * gp + 1];
        const float x0f = floorf(fix), y0f = floorf(fiy);
        const float fx = fix - x0f, fy = fiy - y0f;
        const int x0 = (int)x0f, y0 = (int)y0f;
        const float m = ex[p] * inv_se;

        const bool xv0 = (x0 >= 1) && (x0 <= 64);
        const bool xv1 = (x0 >= 0) && (x0 <= 63);
        const bool yv0 = (y0 >= 1) && (y0 <= 64);
        const bool yv1 = (y0 >= 0) && (y0 <= 63);
        float4 v00 = make_float4(0,0,0,0), v10 = v00, v01 = v00, v11 = v00;
        if (yv0 && xv0) v00 = __ldg(reinterpret_cast<const float4*>(base + ((size_t)(y0 - 1) * WW + (x0 - 1)) * CC));
        if (yv0 && xv1) v10 = __ldg(reinterpret_cast<const float4*>(base + ((size_t)(y0 - 1) * WW + (x0    )) * CC));
        if (yv1 && xv0) v01 = __ldg(reinterpret_cast<const float4*>(base + ((size_t)(y0    ) * WW + (x0 - 1)) * CC));
        if (yv1 && xv1) v11 = __ldg(reinterpret_cast<const float4*>(base + ((size_t)(y0    ) * WW + (x0    )) * CC));

        const float w00 = (1.f - fx) * (1.f - fy) * m;
        const float w10 = fx * (1.f - fy) * m;
        const float w01 = (1.f - fx) * fy * m;
        const float w11 = fx * fy * m;
        acc.x += v00.x * w00 + v10.x * w10 + v01.x * w01 + v11.x * w11;
        acc.y += v00.y * w00 + v10.y * w10 + v01.y * w01 + v11.y * w11;
        acc.z += v00.z * w00 + v10.z * w10 + v01.z * w01 + v11.z * w11;
        acc.w += v00.w * w00 + v10.w * w10 + v01.w * w01 + v11.w * w11;
    }
    *reinterpret_cast<float4*>(out + (size_t)pos * CC + g * GCC + c4) = acc;
}

// ===========================================================================
extern "C" void kernel_launch(void* const* d_in, const int* in_sizes, int n_in,
                              void* d_out, int out_size) {
    const float* x         = (const float*)d_in[0];
    const float* conv_w    = (const float*)d_in[1];
    const float* conv_b    = (const float*)d_in[2];
    const float* in_proj_w = (const float*)d_in[3];
    const float* in_proj_b = (const float*)d_in[4];
    const float* dw_w      = (const float*)d_in[5];
    const float* dw_b      = (const float*)d_in[6];
    const float* ln_g      = (const float*)d_in[7];
    const float* ln_b      = (const float*)d_in[8];
    const float* off_w     = (const float*)d_in[9];
    const float* off_b     = (const float*)d_in[10];
    const float* mask_w    = (const float*)d_in[11];
    const float* mask_b    = (const float*)d_in[12];
    const float* out_w     = (const float*)d_in[13];
    const float* out_b     = (const float*)d_in[14];
    float* out = (float*)d_out;

    float *xt, *y, *xproj, *dg, *samp, *omp, *w1T, *w2P, *w3T, *b2;
    cudaGetSymbolAddress((void**)&xt,    g_xt);
    cudaGetSymbolAddress((void**)&y,     g_y);
    cudaGetSymbolAddress((void**)&xproj, g_xproj);
    cudaGetSymbolAddress((void**)&dg,    g_dg);
    cudaGetSymbolAddress((void**)&samp,  g_samp);
    cudaGetSymbolAddress((void**)&omp,   g_om);
    cudaGetSymbolAddress((void**)&w1T,   g_w1T);
    cudaGetSymbolAddress((void**)&w2P,   g_w2P);
    cudaGetSymbolAddress((void**)&w3T,   g_w3T);
    cudaGetSymbolAddress((void**)&b2,    g_b2);

    static cudaStream_t s1 = nullptr;
    static cudaEvent_t eFork = nullptr, ePrep = nullptr, eConv = nullptr, eProj = nullptr;
    static bool init_done = false;
    if (!init_done) {
        cudaFuncSetAttribute(hmma_gemm_kernel<false>,
                             cudaFuncAttributeMaxDynamicSharedMemorySize, GEMM_SMEM);
        cudaFuncSetAttribute(hmma_gemm_kernel<true>,
                             cudaFuncAttributeMaxDynamicSharedMemorySize, GEMM_SMEM);
        cudaStreamCreateWithFlags(&s1, cudaStreamNonBlocking);
        cudaEventCreateWithFlags(&eFork, cudaEventDisableTiming);
        cudaEventCreateWithFlags(&ePrep, cudaEventDisableTiming);
        cudaEventCreateWithFlags(&eConv, cudaEventDisableTiming);
        cudaEventCreateWithFlags(&eProj, cudaEventDisableTiming);
        init_done = true;
    }

    const dim3 tblk(32, 32);
    const dim3 tgrid(2, 4, BB * HH);
    const dim3 ggrid(NPOS / 64, 2);

    // ---- fork side stream ----
    cudaEventRecord(eFork, 0);
    cudaStreamWaitEvent(s1, eFork, 0);

    // s1: weight prep
    prep_weights_kernel<<<CC, CC, 0, s1>>>(in_proj_w, out_w, off_w, mask_w, off_b, mask_b,
                                           w1T, w3T, w2P, b2);
    cudaEventRecord(ePrep, s1);

    // s0: pack + conv
    pack_x_kernel<<<tgrid, tblk>>>(x, xt);
    hmma_gemm_kernel<false><<<ggrid, 256, GEMM_SMEM>>>(xt, conv_w, conv_b, y);
    cudaEventRecord(eConv, 0);

    // s1: in_proj (parallel with dw branch)
    cudaStreamWaitEvent(s1, eConv, 0);
    hmma_gemm_kernel<false><<<ggrid, 256, GEMM_SMEM, s1>>>(y, w1T, in_proj_b, xproj);
    cudaEventRecord(eProj, s1);

    // s0: dw+LN+GELU -> off_mask GEMM
    dw_ln_gelu_kernel<<<NPOS / 8, 256>>>(y, dw_w, dw_b, ln_g, ln_b, dg);
    cudaStreamWaitEvent(0, ePrep, 0);
    hmma_gemm_kernel<false><<<ggrid, 256, GEMM_SMEM>>>(dg, w2P, b2, omp);

    // join: sampler needs xproj (s1) + omp (s0)
    cudaStreamWaitEvent(0, eProj, 0);
    sampler_kernel<<<NPOS / 4, 128>>>(xproj, omp, samp);

    // out_proj writes NCHW directly
    hmma_gemm_kernel<true><<<ggrid, 256, GEMM_SMEM>>>(samp, w3T, out_b, out);
}